// round 14
// baseline (speedup 1.0000x reference)
#include <cuda_runtime.h>
#include <cuda_bf16.h>
#include <cstddef>

// CompressK: ragged strided chunk mean-pool (NSA K compression).
//   k:          [total_tokens, H, D] fp32   (H*D = 512 here)
//   cu_seqlens: [B+1] int32
//   kernel_size, kernel_stride: int32 scalars (device)
// Output: compressed_k [NC, H, D] fp32 followed by (B+1) compressed
// cu_seqlens as float values.
//
// R13: one chunk per CTA (G=1), 2044 CTAs x 128 threads — the highest
// independent-load-stream regime measured in this session (R2's main
// kernel: ~12.9 TB/s L2) — with the compressed-cu_seqlens tail fused
// into block 0 (R2 lost 4.4us to a serialized second launch). Plain
// cached float4 loads and plain stores: every exotic variant (cache
// hints, v8.b32, cp.async, smem combines) measured worse on wall due
// to weaker cross-replay L2 retention and stream duty-cycle loss.

#define HD    512          // H * D
#define HD4   (HD / 4)     // float4 lanes per row (= block size)
#define KS_C  32
#define ST_C  16

__global__ void __launch_bounds__(HD4)
compressk_kernel(const float4* __restrict__ k4,
                 const int*    __restrict__ cu,
                 const int*    __restrict__ p_ks,
                 const int*    __restrict__ p_st,
                 float4*       __restrict__ out4,
                 float*        __restrict__ out_tail,
                 int B, int tail_n)
{
    const int tid = threadIdx.x;
    const int c   = blockIdx.x;          // chunk id
    const int ks  = __ldg(p_ks);
    const int st  = __ldg(p_st);

    // Fused tail: block 0 writes the compressed cu_seqlens.
    if (c == 0 && tid < tail_n) {
        int acc = 0;
        for (int j = 0; j < tid; j++) {
            const int len = __ldg(cu + j + 1) - __ldg(cu + j);
            acc += (len >= ks) ? (len - ks) / st + 1 : 0;
        }
        out_tail[tid] = (float)acc;
    }

    // Map chunk id -> starting token via a scan over the (tiny) cu_seqlens.
    int start_tok = 0;
    bool found = false;
    {
        int cacc = 0;
        #pragma unroll 4
        for (int i = 0; i < B; i++) {
            const int s0  = __ldg(cu + i);
            const int s1  = __ldg(cu + i + 1);
            const int len = s1 - s0;
            const int nc  = (len >= ks) ? (len - ks) / st + 1 : 0;
            if (!found && c >= cacc && c < cacc + nc) {
                start_tok = s0 + (c - cacc) * st;
                found     = true;
            }
            cacc += nc;
        }
    }
    if (!found) return;

    const float4* row = k4 + (size_t)start_tok * HD4 + tid;
    const float   inv = 1.0f / (float)ks;

    if (ks == KS_C) {
        // Fast path: fully unrolled 32 independent float4 loads.
        float4 s = make_float4(0.f, 0.f, 0.f, 0.f);
        #pragma unroll
        for (int t = 0; t < KS_C; t++) {
            const float4 v = row[(size_t)t * HD4];
            s.x += v.x; s.y += v.y; s.z += v.z; s.w += v.w;
        }
        s.x *= inv; s.y *= inv; s.z *= inv; s.w *= inv;
        out4[(size_t)c * HD4 + tid] = s;
    } else {
        float4 s = make_float4(0.f, 0.f, 0.f, 0.f);
        #pragma unroll 8
        for (int t = 0; t < ks; t++) {
            const float4 v = row[(size_t)t * HD4];
            s.x += v.x; s.y += v.y; s.z += v.z; s.w += v.w;
        }
        s.x *= inv; s.y *= inv; s.z *= inv; s.w *= inv;
        out4[(size_t)c * HD4 + tid] = s;
    }
}

extern "C" void kernel_launch(void* const* d_in, const int* in_sizes, int n_in,
                              void* d_out, int out_size)
{
    const float4* k4   = (const float4*)d_in[0];
    const int*    cu   = (const int*)d_in[1];
    const int*    p_ks = (const int*)d_in[2];
    const int*    p_st = (const int*)d_in[3];

    const int B = in_sizes[1] - 1;

    // Chunk count from output size; remainder = appended compressed cu_seqlens.
    const int NC   = out_size / HD;
    const int tail = out_size - NC * HD;
    if (NC <= 0) return;

    compressk_kernel<<<NC, HD4>>>(
        k4, cu, p_ks, p_st,
        (float4*)d_out,
        (float*)d_out + (size_t)NC * HD,
        B, tail);
}

// round 15
// speedup vs baseline: 1.0150x; 1.0150x over previous
#include <cuda_runtime.h>
#include <cuda_bf16.h>
#include <cstddef>

// CompressK: ragged strided chunk mean-pool (NSA K compression).
//   k:          [total_tokens, H, D] fp32   (H*D = 512 here)
//   cu_seqlens: [B+1] int32
//   kernel_size, kernel_stride: int32 scalars (device)
// Output: compressed_k [NC, H, D] fp32 followed by (B+1) compressed
// cu_seqlens as float values.
//
// R14 = the 10.7us winner (G=2 streaming half-sums, 128-thr blocks,
// 1027 CTAs, plain float4 loads/stores, fused tail) with the three
// 16-row half-sums INTERLEAVED in rounds of 12 loads (4 rows x 3
// halves in flight, 3 independent accumulator chains) to raise the
// front-batched MLP per warp at unchanged traffic/warp count. Loads
// are unconditional (trailing half of a partial group is clamped
// in-bounds and only combined into a stored chunk when gn==2).

#define HD    512          // H * D
#define HD4   (HD / 4)     // float4 lanes per row (= block size)
#define G     2            // chunks per block (fast path)
#define KS_C  32
#define ST_C  16

__global__ void __launch_bounds__(HD4)
compressk_kernel(const float4* __restrict__ k4,
                 const int*    __restrict__ cu,
                 const int*    __restrict__ p_ks,
                 const int*    __restrict__ p_st,
                 float4*       __restrict__ out4,
                 float*        __restrict__ out_tail,
                 int B, int tail_n)
{
    const int tid = threadIdx.x;
    const int g   = blockIdx.x;
    const int ks  = __ldg(p_ks);
    const int st  = __ldg(p_st);
    const int T   = __ldg(cu + B);       // total tokens

    // Fused tail: block 0 writes the compressed cu_seqlens.
    if (g == 0 && tid < tail_n) {
        int acc = 0;
        for (int j = 0; j < tid; j++) {
            const int len = __ldg(cu + j + 1) - __ldg(cu + j);
            acc += (len >= ks) ? (len - ks) / st + 1 : 0;
        }
        out_tail[tid] = (float)acc;
    }

    // Locate this block's chunk group via a scan over the (tiny) cu_seqlens.
    int start_tok = 0, chunk0 = 0, gn = 0;
    {
        int gacc = 0, cacc = 0;
        #pragma unroll 4
        for (int i = 0; i < B; i++) {
            const int s0  = __ldg(cu + i);
            const int s1  = __ldg(cu + i + 1);
            const int len = s1 - s0;
            const int nc  = (len >= ks) ? (len - ks) / st + 1 : 0;
            const int ng  = (nc + G - 1) / G;
            if (g >= gacc && g < gacc + ng) {
                const int gi = g - gacc;
                const int c0 = gi * G;
                gn        = min(G, nc - c0);
                chunk0    = cacc + c0;
                start_tok = s0 + c0 * st;
            }
            gacc += ng;
            cacc += nc;
        }
    }
    if (gn <= 0) return;

    const float inv = 1.0f / (float)ks;

    if (ks == KS_C && st == ST_C) {
        // ── Fast path: interleaved 3-half streaming sums ────────────────
        // Halves 0,1 always in-bounds; half 2 clamped (only used gn==2,
        // where it is in-bounds by construction).
        const int r2 = min(start_tok + 2 * ST_C, T - ST_C);
        const float4* p0 = k4 + (size_t)start_tok * HD4 + tid;
        const float4* p1 = p0 + (size_t)ST_C * HD4;
        const float4* p2 = k4 + (size_t)r2 * HD4 + tid;

        float4 a0 = make_float4(0.f, 0.f, 0.f, 0.f);
        float4 a1 = make_float4(0.f, 0.f, 0.f, 0.f);
        float4 a2 = make_float4(0.f, 0.f, 0.f, 0.f);

        #pragma unroll
        for (int r = 0; r < 4; r++) {
            float4 x0[4], x1[4], x2[4];
            #pragma unroll
            for (int j = 0; j < 4; j++)
                x0[j] = p0[(size_t)(r * 4 + j) * HD4];
            #pragma unroll
            for (int j = 0; j < 4; j++)
                x1[j] = p1[(size_t)(r * 4 + j) * HD4];
            #pragma unroll
            for (int j = 0; j < 4; j++)
                x2[j] = p2[(size_t)(r * 4 + j) * HD4];

            #pragma unroll
            for (int j = 0; j < 4; j++) {
                a0.x += x0[j].x; a0.y += x0[j].y;
                a0.z += x0[j].z; a0.w += x0[j].w;
                a1.x += x1[j].x; a1.y += x1[j].y;
                a1.z += x1[j].z; a1.w += x1[j].w;
                a2.x += x2[j].x; a2.y += x2[j].y;
                a2.z += x2[j].z; a2.w += x2[j].w;
            }
        }

        float4 o;
        o.x = (a0.x + a1.x) * inv;
        o.y = (a0.y + a1.y) * inv;
        o.z = (a0.z + a1.z) * inv;
        o.w = (a0.w + a1.w) * inv;
        out4[(size_t)chunk0 * HD4 + tid] = o;

        if (gn == 2) {
            o.x = (a1.x + a2.x) * inv;
            o.y = (a1.y + a2.y) * inv;
            o.z = (a1.z + a2.z) * inv;
            o.w = (a1.w + a2.w) * inv;
            out4[(size_t)(chunk0 + 1) * HD4 + tid] = o;
        }
    } else {
        // ── Generic fallback: naive per-chunk sum ───────────────────────
        for (int h = 0; h < gn; h++) {
            const float4* p = k4 + (size_t)(start_tok + h * st) * HD4 + tid;
            float4 s = make_float4(0.f, 0.f, 0.f, 0.f);
            #pragma unroll 8
            for (int t = 0; t < ks; t++) {
                const float4 v = p[(size_t)t * HD4];
                s.x += v.x; s.y += v.y; s.z += v.z; s.w += v.w;
            }
            s.x *= inv; s.y *= inv; s.z *= inv; s.w *= inv;
            out4[(size_t)(chunk0 + h) * HD4 + tid] = s;
        }
    }
}

extern "C" void kernel_launch(void* const* d_in, const int* in_sizes, int n_in,
                              void* d_out, int out_size)
{
    const float4* k4   = (const float4*)d_in[0];
    const int*    cu   = (const int*)d_in[1];
    const int*    p_ks = (const int*)d_in[2];
    const int*    p_st = (const int*)d_in[3];

    const int B = in_sizes[1] - 1;

    // Chunk count from output size; remainder = appended compressed cu_seqlens.
    const int NC   = out_size / HD;
    const int tail = out_size - NC * HD;
    if (NC <= 0) return;

    // Upper bound on groups: ceil(NC/G) plus one partial group per sequence.
    const int max_groups = (NC + G - 1) / G + B;

    compressk_kernel<<<max_groups, HD4>>>(
        k4, cu, p_ks, p_st,
        (float4*)d_out,
        (float*)d_out + (size_t)NC * HD,
        B, tail);
}